// round 15
// baseline (speedup 1.0000x reference)
#include <cuda_runtime.h>
#include <cuda_bf16.h>
#include <cstdint>
#include <math.h>

#define B_ 4
#define T_ 2048
#define C_ 1024
#define H_ 16
#define D_ 64
#define WIN_ 256

#define GK 1024            // K of both GEMMs
#define CHUNK 32           // K elements per SMEM stage
#define NCHUNK (GK / CHUNK)

#define PW 20              // smem pitch in 32-bit words per row (16 data + 4 pad)
#define AW_B (128 * PW * 4)        // A plane bytes per stage (10240)
#define BW_B (256 * PW * 4)        // B plane bytes per stage (20480)
#define STAGE_B (2 * AW_B + 2 * BW_B)  // 61440
#define GEMM_SMEM (3 * STAGE_B)        // 184320, 3-stage pipeline

// Scratch (allocation-free rule: __device__ globals)
__device__ __nv_bfloat16 g_xhi[(size_t)B_ * T_ * C_];
__device__ __nv_bfloat16 g_xlo[(size_t)B_ * T_ * C_];
__device__ __nv_bfloat16 g_ahi[(size_t)B_ * T_ * C_];
__device__ __nv_bfloat16 g_alo[(size_t)B_ * T_ * C_];
__device__ __nv_bfloat16 g_w1hi[(size_t)3 * C_ * C_];
__device__ __nv_bfloat16 g_w1lo[(size_t)3 * C_ * C_];
__device__ __nv_bfloat16 g_w2hi[(size_t)C_ * C_];
__device__ __nv_bfloat16 g_w2lo[(size_t)C_ * C_];
__device__ __nv_bfloat16 g_qkvhi[(size_t)B_ * T_ * 3 * C_];
__device__ __nv_bfloat16 g_qkvlo[(size_t)B_ * T_ * 3 * C_];

// ---------------------------------------------------------------------------
// helpers
// ---------------------------------------------------------------------------
__device__ __forceinline__ uint32_t smem_u32(const void* p) {
    uint32_t a;
    asm("{ .reg .u64 t; cvta.to.shared.u64 t, %1; cvt.u32.u64 %0, t; }" : "=r"(a) : "l"(p));
    return a;
}
__device__ __forceinline__ void cp16(uint32_t dst, const void* src) {
    asm volatile("cp.async.ca.shared.global [%0], [%1], 16;" :: "r"(dst), "l"(src));
}
__device__ __forceinline__ void mma_bf16(float* c, const uint32_t* a, const uint32_t* b) {
    asm volatile(
        "mma.sync.aligned.m16n8k16.row.col.f32.bf16.bf16.f32 "
        "{%0,%1,%2,%3}, {%4,%5,%6,%7}, {%8,%9}, {%0,%1,%2,%3};"
        : "+f"(c[0]), "+f"(c[1]), "+f"(c[2]), "+f"(c[3])
        : "r"(a[0]), "r"(a[1]), "r"(a[2]), "r"(a[3]), "r"(b[0]), "r"(b[1]));
}
__device__ __forceinline__ void ldsm4(uint32_t* r, uint32_t addr) {
    asm volatile("ldmatrix.sync.aligned.m8n8.x4.shared.b16 {%0,%1,%2,%3}, [%4];"
                 : "=r"(r[0]), "=r"(r[1]), "=r"(r[2]), "=r"(r[3]) : "r"(addr));
}
__device__ __forceinline__ void ldsm4t(uint32_t* r, uint32_t addr) {
    asm volatile("ldmatrix.sync.aligned.m8n8.x4.trans.shared.b16 {%0,%1,%2,%3}, [%4];"
                 : "=r"(r[0]), "=r"(r[1]), "=r"(r[2]), "=r"(r[3]) : "r"(addr));
}
__device__ __forceinline__ uint32_t pack_hi(float a, float b, uint32_t* lo) {
    __nv_bfloat162 h = __floats2bfloat162_rn(a, b);
    __nv_bfloat162 l = __floats2bfloat162_rn(a - __low2float(h), b - __high2float(h));
    *lo = *(uint32_t*)&l;
    return *(uint32_t*)&h;
}

// ---------------------------------------------------------------------------
// fp32 -> (hi, lo) bf16 split (used for the three raw inputs only)
// ---------------------------------------------------------------------------
__global__ __launch_bounds__(256) void split_bf16(const float* __restrict__ in,
                                                  __nv_bfloat16* __restrict__ hi,
                                                  __nv_bfloat16* __restrict__ lo,
                                                  int n4) {
    int i = blockIdx.x * blockDim.x + threadIdx.x;
    if (i >= n4) return;
    float4 v = ((const float4*)in)[i];
    uint32_t l0, l1, h0, h1;
    h0 = pack_hi(v.x, v.y, &l0);
    h1 = pack_hi(v.z, v.w, &l1);
    ((uint32_t*)hi)[2 * i] = h0;
    ((uint32_t*)hi)[2 * i + 1] = h1;
    ((uint32_t*)lo)[2 * i] = l0;
    ((uint32_t*)lo)[2 * i + 1] = l1;
}

// ---------------------------------------------------------------------------
// 3-term split-bf16 GEMM (NT): C[m,n] = sum_k A[m,k] * B[n,k], fp32 accum.
// CTA 128x256, 8 warps (2M x 4N), warp tile 64x64. K chunks of 32,
// 3-stage cp.async pipeline; ldmatrix fragment feeds.
// SPLIT=true: write C as bf16 hi/lo planes (fused split). else fp32.
// ---------------------------------------------------------------------------
template <bool SPLIT>
__global__ __launch_bounds__(256, 1) void gemm_split(const __nv_bfloat16* __restrict__ Ahi,
                                                     const __nv_bfloat16* __restrict__ Alo,
                                                     const __nv_bfloat16* __restrict__ Bhi,
                                                     const __nv_bfloat16* __restrict__ Blo,
                                                     float* __restrict__ Cf,
                                                     __nv_bfloat16* __restrict__ Chi,
                                                     __nv_bfloat16* __restrict__ Clo,
                                                     int N) {
    extern __shared__ __align__(1024) uint32_t sw[];
    const int tid = threadIdx.x;
    const int wid = tid >> 5, lane = tid & 31;
    const int warp_m = wid >> 2, warp_n = wid & 3;
    const int gr = lane >> 2, lk = lane & 3;
    const int m0 = blockIdx.y * 128, n0 = blockIdx.x * 256;

    // producers
    const int ldrow = tid >> 1, half = tid & 1;
    const __nv_bfloat16* a_hi = Ahi + (long)(m0 + ldrow) * GK + half * 16;
    const __nv_bfloat16* a_lo = Alo + (long)(m0 + ldrow) * GK + half * 16;
    const __nv_bfloat16* b_hi0 = Bhi + (long)(n0 + ldrow) * GK + half * 16;
    const __nv_bfloat16* b_lo0 = Blo + (long)(n0 + ldrow) * GK + half * 16;
    const __nv_bfloat16* b_hi1 = b_hi0 + (long)128 * GK;
    const __nv_bfloat16* b_lo1 = b_lo0 + (long)128 * GK;
    const uint32_t sbase = smem_u32(sw);
    const uint32_t drA = (uint32_t)ldrow * (PW * 4) + (uint32_t)half * 32;
    const uint32_t drB0 = drA;
    const uint32_t drB1 = drA + 128u * (PW * 4);

#define ISSUE(stb, cc) do {                                                   \
    const uint32_t _s = (stb);                                                \
    const long _k = (long)(cc) * CHUNK;                                       \
    cp16(_s + drA, a_hi + _k);                cp16(_s + drA + 16, a_hi + _k + 8);   \
    cp16(_s + AW_B + drA, a_lo + _k);         cp16(_s + AW_B + drA + 16, a_lo + _k + 8); \
    cp16(_s + 2 * AW_B + drB0, b_hi0 + _k);   cp16(_s + 2 * AW_B + drB0 + 16, b_hi0 + _k + 8); \
    cp16(_s + 2 * AW_B + drB1, b_hi1 + _k);   cp16(_s + 2 * AW_B + drB1 + 16, b_hi1 + _k + 8); \
    cp16(_s + 2 * AW_B + BW_B + drB0, b_lo0 + _k); cp16(_s + 2 * AW_B + BW_B + drB0 + 16, b_lo0 + _k + 8); \
    cp16(_s + 2 * AW_B + BW_B + drB1, b_lo1 + _k); cp16(_s + 2 * AW_B + BW_B + drB1 + 16, b_lo1 + _k + 8); \
} while (0)

    // ldmatrix per-lane offsets within a plane
    const uint32_t aoff = (uint32_t)(warp_m * 64 + (lane & 15)) * (PW * 4) + ((uint32_t)(lane >> 4) << 4);
    const uint32_t boff = (uint32_t)(warp_n * 64 + ((lane >> 4) & 1) * 8 + (lane & 7)) * (PW * 4)
                          + (((uint32_t)(lane >> 3) & 1) << 4);

    float acc[4][8][4];
#pragma unroll
    for (int mt = 0; mt < 4; mt++)
#pragma unroll
        for (int nt = 0; nt < 8; nt++)
#pragma unroll
            for (int i = 0; i < 4; i++) acc[mt][nt][i] = 0.f;

    // prologue: stages 0, 1
    ISSUE(sbase, 0);
    asm volatile("cp.async.commit_group;" ::: "memory");
    ISSUE(sbase + STAGE_B, 1);
    asm volatile("cp.async.commit_group;" ::: "memory");

    for (int c = 0; c < NCHUNK; ++c) {
        if (c + 1 < NCHUNK) {
            asm volatile("cp.async.wait_group 1;" ::: "memory");
        } else {
            asm volatile("cp.async.wait_group 0;" ::: "memory");
        }
        __syncthreads();
        if (c + 2 < NCHUNK) {
            ISSUE(sbase + (uint32_t)((c + 2) % 3) * STAGE_B, c + 2);
            asm volatile("cp.async.commit_group;" ::: "memory");
        }

        const uint32_t stb = sbase + (uint32_t)(c % 3) * STAGE_B;
        const uint32_t ah_b = stb + aoff;
        const uint32_t al_b = stb + AW_B + aoff;
        const uint32_t bh_b = stb + 2 * AW_B + boff;
        const uint32_t bl_b = stb + 2 * AW_B + BW_B + boff;
#pragma unroll
        for (int s = 0; s < 2; s++) {
            const uint32_t ks = (uint32_t)s * 32u;
            uint32_t ah[4][4], al[4][4], bh[4][4], bl[4][4];
#pragma unroll
            for (int mt = 0; mt < 4; mt++) ldsm4(ah[mt], ah_b + (uint32_t)mt * 1280u + ks);
#pragma unroll
            for (int p = 0; p < 4; p++) ldsm4(bh[p], bh_b + (uint32_t)p * 1280u + ks);
#pragma unroll
            for (int mt = 0; mt < 4; mt++)
#pragma unroll
                for (int nt = 0; nt < 8; nt++)
                    mma_bf16(acc[mt][nt], ah[mt], &bh[nt >> 1][(nt & 1) * 2]);   // hi*hi
#pragma unroll
            for (int p = 0; p < 4; p++) ldsm4(bl[p], bl_b + (uint32_t)p * 1280u + ks);
#pragma unroll
            for (int mt = 0; mt < 4; mt++)
#pragma unroll
                for (int nt = 0; nt < 8; nt++)
                    mma_bf16(acc[mt][nt], ah[mt], &bl[nt >> 1][(nt & 1) * 2]);   // hi*lo
#pragma unroll
            for (int mt = 0; mt < 4; mt++) ldsm4(al[mt], al_b + (uint32_t)mt * 1280u + ks);
#pragma unroll
            for (int mt = 0; mt < 4; mt++)
#pragma unroll
                for (int nt = 0; nt < 8; nt++)
                    mma_bf16(acc[mt][nt], al[mt], &bh[nt >> 1][(nt & 1) * 2]);   // lo*hi
        }
    }
#undef ISSUE

    // epilogue
#pragma unroll
    for (int mt = 0; mt < 4; mt++) {
        const int m = m0 + warp_m * 64 + mt * 16 + gr;
#pragma unroll
        for (int nt = 0; nt < 8; nt++) {
            const int n = n0 + warp_n * 64 + nt * 8 + 2 * lk;
            if (SPLIT) {
                uint32_t lo0, lo1;
                uint32_t hi0 = pack_hi(acc[mt][nt][0], acc[mt][nt][1], &lo0);
                uint32_t hi1 = pack_hi(acc[mt][nt][2], acc[mt][nt][3], &lo1);
                *(uint32_t*)&Chi[(long)m * N + n] = hi0;
                *(uint32_t*)&Clo[(long)m * N + n] = lo0;
                *(uint32_t*)&Chi[(long)(m + 8) * N + n] = hi1;
                *(uint32_t*)&Clo[(long)(m + 8) * N + n] = lo1;
            } else {
                *(float2*)&Cf[(long)m * N + n] = make_float2(acc[mt][nt][0], acc[mt][nt][1]);
                *(float2*)&Cf[(long)(m + 8) * N + n] = make_float2(acc[mt][nt][2], acc[mt][nt][3]);
            }
        }
    }
}

// ---------------------------------------------------------------------------
// Tensor-core sliding-window attention (FA2 style, split-bf16 3-term MMA).
// Writes output directly as bf16 hi/lo planes (fused split).
// ---------------------------------------------------------------------------
#define APITCH 144
#define ATB 9216
#define ASTAGE0 18432
#define ASTAGE_SZ (4 * ATB)
#define ATT_SMEM (ASTAGE0 + 2 * ASTAGE_SZ)

__global__ __launch_bounds__(128) void attn_mma(const __nv_bfloat16* __restrict__ qhi,
                                                const __nv_bfloat16* __restrict__ qlo,
                                                __nv_bfloat16* __restrict__ ohi,
                                                __nv_bfloat16* __restrict__ olo) {
    extern __shared__ __align__(1024) unsigned char asm_[];
    const uint32_t sb = smem_u32(asm_);
    const int qt = blockIdx.x, h = blockIdx.y, b = blockIdx.z;
    const int q0 = qt * 64;
    const int tid = threadIdx.x;
    const int warp = tid >> 5, lane = tid & 31;
    const int gr = lane >> 2, lk = lane & 3;

#pragma unroll
    for (int g = tid; g < 512; g += 128) {
        const int r = g >> 3, c8 = (g & 7);
        const long go = ((long)(b * T_ + q0 + r)) * (3 * C_) + h * D_ + c8 * 8;
        const uint32_t d = sb + (uint32_t)r * APITCH + (uint32_t)c8 * 16;
        cp16(d, qhi + go);
        cp16(d + ATB, qlo + go);
    }
    const int kt0 = (qt >= 4) ? (qt - 4) : 0;
    {
#pragma unroll
        for (int g = tid; g < 512; g += 128) {
            const int r = g >> 3, c8 = (g & 7);
            const long gk = ((long)(b * T_ + kt0 * 64 + r)) * (3 * C_) + C_ + h * D_ + c8 * 8;
            const uint32_t d = sb + ASTAGE0 + (uint32_t)r * APITCH + (uint32_t)c8 * 16;
            cp16(d, qhi + gk);
            cp16(d + ATB, qlo + gk);
            cp16(d + 2 * ATB, qhi + gk + C_);
            cp16(d + 3 * ATB, qlo + gk + C_);
        }
    }
    asm volatile("cp.async.commit_group;" ::: "memory");

    const uint32_t aq = sb + (uint32_t)(warp * 16 + (lane & 15)) * APITCH + ((uint32_t)(lane >> 4) << 4);
    const uint32_t bk_off = (uint32_t)(((lane >> 4) & 1) * 8 + (lane & 7)) * APITCH + (((uint32_t)(lane >> 3) & 1) << 4);
    const uint32_t bv_off = (uint32_t)((lane & 7) + ((lane >> 3) & 1) * 8) * APITCH + ((uint32_t)(lane >> 4) << 4);

    float o[8][4];
#pragma unroll
    for (int i = 0; i < 8; i++)
#pragma unroll
        for (int j = 0; j < 4; j++) o[i][j] = 0.f;
    float m0 = -1e30f, m1 = -1e30f, l0 = 0.f, l1 = 0.f;

    for (int kt = kt0; kt <= qt; kt++) {
        const uint32_t stg = sb + ASTAGE0 + (uint32_t)((kt - kt0) & 1) * ASTAGE_SZ;
        if (kt < qt) {
            const uint32_t nst = sb + ASTAGE0 + (uint32_t)((kt + 1 - kt0) & 1) * ASTAGE_SZ;
#pragma unroll
            for (int g = tid; g < 512; g += 128) {
                const int r = g >> 3, c8 = (g & 7);
                const long gk = ((long)(b * T_ + (kt + 1) * 64 + r)) * (3 * C_) + C_ + h * D_ + c8 * 8;
                const uint32_t d = nst + (uint32_t)r * APITCH + (uint32_t)c8 * 16;
                cp16(d, qhi + gk);
                cp16(d + ATB, qlo + gk);
                cp16(d + 2 * ATB, qhi + gk + C_);
                cp16(d + 3 * ATB, qlo + gk + C_);
            }
            asm volatile("cp.async.commit_group;" ::: "memory");
            asm volatile("cp.async.wait_group 1;" ::: "memory");
        } else {
            asm volatile("cp.async.wait_group 0;" ::: "memory");
        }
        __syncthreads();

        // ---- S = Q K^T ----
        float sc[8][4];
#pragma unroll
        for (int i = 0; i < 8; i++)
#pragma unroll
            for (int j = 0; j < 4; j++) sc[i][j] = 0.f;
        const uint32_t bk = stg + bk_off;
#pragma unroll
        for (int ks = 0; ks < 4; ks++) {
            uint32_t qh[4], ql[4];
            ldsm4(qh, aq + ks * 32);
            ldsm4(ql, aq + ATB + ks * 32);
#pragma unroll
            for (int p = 0; p < 4; p++) {
                uint32_t kh[4], kl[4];
                ldsm4(kh, bk + (uint32_t)p * (16 * APITCH) + ks * 32);
                mma_bf16(sc[2 * p], qh, kh);
                mma_bf16(sc[2 * p + 1], qh, kh + 2);
                ldsm4(kl, bk + ATB + (uint32_t)p * (16 * APITCH) + ks * 32);
                mma_bf16(sc[2 * p], qh, kl);
                mma_bf16(sc[2 * p + 1], qh, kl + 2);
                mma_bf16(sc[2 * p], ql, kh);
                mma_bf16(sc[2 * p + 1], ql, kh + 2);
            }
        }

        // ---- scale + mask ----
        const int qa = q0 + warp * 16 + gr;
        const int qb = qa + 8;
#pragma unroll
        for (int nt = 0; nt < 8; nt++) {
            const int j0 = kt * 64 + nt * 8 + 2 * lk;
#pragma unroll
            for (int i = 0; i < 4; i++) {
                const int q = (i >= 2) ? qb : qa;
                const int j = j0 + (i & 1);
                const float s = sc[nt][i] * 0.125f;
                sc[nt][i] = (j <= q && j > q - WIN_) ? s : -1e30f;
            }
        }

        // ---- online softmax ----
        float mx0 = -1e30f, mx1 = -1e30f;
#pragma unroll
        for (int nt = 0; nt < 8; nt++) {
            mx0 = fmaxf(mx0, fmaxf(sc[nt][0], sc[nt][1]));
            mx1 = fmaxf(mx1, fmaxf(sc[nt][2], sc[nt][3]));
        }
        mx0 = fmaxf(mx0, __shfl_xor_sync(0xffffffffu, mx0, 1));
        mx0 = fmaxf(mx0, __shfl_xor_sync(0xffffffffu, mx0, 2));
        mx1 = fmaxf(mx1, __shfl_xor_sync(0xffffffffu, mx1, 1));
        mx1 = fmaxf(mx1, __shfl_xor_sync(0xffffffffu, mx1, 2));
        const float mn0 = fmaxf(m0, mx0), mn1 = fmaxf(m1, mx1);
        const float cr0 = __expf(m0 - mn0), cr1 = __expf(m1 - mn1);
        m0 = mn0; m1 = mn1;
        float s0 = 0.f, s1 = 0.f;
#pragma unroll
        for (int nt = 0; nt < 8; nt++) {
            sc[nt][0] = __expf(sc[nt][0] - mn0);
            sc[nt][1] = __expf(sc[nt][1] - mn0);
            sc[nt][2] = __expf(sc[nt][2] - mn1);
            sc[nt][3] = __expf(sc[nt][3] - mn1);
            s0 += sc[nt][0] + sc[nt][1];
            s1 += sc[nt][2] + sc[nt][3];
        }
        s0 += __shfl_xor_sync(0xffffffffu, s0, 1);
        s0 += __shfl_xor_sync(0xffffffffu, s0, 2);
        s1 += __shfl_xor_sync(0xffffffffu, s1, 1);
        s1 += __shfl_xor_sync(0xffffffffu, s1, 2);
        l0 = l0 * cr0 + s0;
        l1 = l1 * cr1 + s1;
#pragma unroll
        for (int dt = 0; dt < 8; dt++) {
            o[dt][0] *= cr0; o[dt][1] *= cr0;
            o[dt][2] *= cr1; o[dt][3] *= cr1;
        }

        // ---- O += P V ----
        const uint32_t bv = stg + 2 * ATB + bv_off;
#pragma unroll
        for (int ks = 0; ks < 4; ks++) {
            uint32_t af[4], afl[4];
#pragma unroll
            for (int half = 0; half < 2; half++) {
                af[2 * half] = pack_hi(sc[2 * ks + half][0], sc[2 * ks + half][1], &afl[2 * half]);
                af[2 * half + 1] = pack_hi(sc[2 * ks + half][2], sc[2 * ks + half][3], &afl[2 * half + 1]);
            }
#pragma unroll
            for (int p = 0; p < 4; p++) {
                uint32_t vh[4], vl[4];
                ldsm4t(vh, bv + (uint32_t)ks * (16 * APITCH) + (uint32_t)p * 32);
                mma_bf16(o[2 * p], af, vh);
                mma_bf16(o[2 * p + 1], af, vh + 2);
                ldsm4t(vl, bv + ATB + (uint32_t)ks * (16 * APITCH) + (uint32_t)p * 32);
                mma_bf16(o[2 * p], af, vl);
                mma_bf16(o[2 * p + 1], af, vl + 2);
                mma_bf16(o[2 * p], afl, vh);
                mma_bf16(o[2 * p + 1], afl, vh + 2);
            }
        }
        __syncthreads();
    }

    // ---- normalize + fused-split store ----
    const float i0 = 1.f / l0, i1 = 1.f / l1;
    const int qa = q0 + warp * 16 + gr;
#pragma unroll
    for (int dt = 0; dt < 8; dt++) {
        const int col = h * D_ + dt * 8 + 2 * lk;
        uint32_t lo0, lo1;
        uint32_t hi0 = pack_hi(o[dt][0] * i0, o[dt][1] * i0, &lo0);
        uint32_t hi1 = pack_hi(o[dt][2] * i1, o[dt][3] * i1, &lo1);
        *(uint32_t*)&ohi[((long)(b * T_ + qa)) * C_ + col] = hi0;
        *(uint32_t*)&olo[((long)(b * T_ + qa)) * C_ + col] = lo0;
        *(uint32_t*)&ohi[((long)(b * T_ + qa + 8)) * C_ + col] = hi1;
        *(uint32_t*)&olo[((long)(b * T_ + qa + 8)) * C_ + col] = lo1;
    }
}

// ---------------------------------------------------------------------------
extern "C" void kernel_launch(void* const* d_in, const int* in_sizes, int n_in,
                              void* d_out, int out_size) {
    const float* x     = (const float*)d_in[0];  // [B,T,C]
    const float* Wqkv  = (const float*)d_in[1];  // [3C, C]
    const float* Wproj = (const float*)d_in[2];  // [C, C]
    float* out = (float*)d_out;                  // [B,T,C]

    __nv_bfloat16 *xhi, *xlo, *ahi, *alo, *w1hi, *w1lo, *w2hi, *w2lo, *qvh, *qvl;
    cudaGetSymbolAddress((void**)&xhi, g_xhi);
    cudaGetSymbolAddress((void**)&xlo, g_xlo);
    cudaGetSymbolAddress((void**)&ahi, g_ahi);
    cudaGetSymbolAddress((void**)&alo, g_alo);
    cudaGetSymbolAddress((void**)&w1hi, g_w1hi);
    cudaGetSymbolAddress((void**)&w1lo, g_w1lo);
    cudaGetSymbolAddress((void**)&w2hi, g_w2hi);
    cudaGetSymbolAddress((void**)&w2lo, g_w2lo);
    cudaGetSymbolAddress((void**)&qvh, g_qkvhi);
    cudaGetSymbolAddress((void**)&qvl, g_qkvlo);

    const int M = B_ * T_;  // 8192
    cudaFuncSetAttribute(gemm_split<true>, cudaFuncAttributeMaxDynamicSharedMemorySize, GEMM_SMEM);
    cudaFuncSetAttribute(gemm_split<false>, cudaFuncAttributeMaxDynamicSharedMemorySize, GEMM_SMEM);
    cudaFuncSetAttribute(attn_mma, cudaFuncAttributeMaxDynamicSharedMemorySize, ATT_SMEM);

    // 0) split raw inputs into bf16 hi/lo planes
    {
        int nx = M * C_ / 4;
        split_bf16<<<(nx + 255) / 256, 256>>>(x, xhi, xlo, nx);
        int nw1 = 3 * C_ * C_ / 4;
        split_bf16<<<(nw1 + 255) / 256, 256>>>(Wqkv, w1hi, w1lo, nw1);
        int nw2 = C_ * C_ / 4;
        split_bf16<<<(nw2 + 255) / 256, 256>>>(Wproj, w2hi, w2lo, nw2);
    }

    // 1) qkv = x @ Wqkv^T -> bf16 hi/lo planes directly (fused split)
    {
        dim3 grid(3 * C_ / 256, M / 128);
        gemm_split<true><<<grid, 256, GEMM_SMEM>>>(xhi, xlo, w1hi, w1lo, nullptr, qvh, qvl, 3 * C_);
    }

    // 2) tensor-core windowed attention -> bf16 hi/lo planes (fused split)
    {
        dim3 grid(T_ / 64, H_, B_);
        attn_mma<<<grid, 128, ATT_SMEM>>>(qvh, qvl, ahi, alo);
    }

    // 3) out = att @ Wproj^T  [8192, 1024] fp32
    {
        dim3 grid(C_ / 256, M / 128);
        gemm_split<false><<<grid, 256, GEMM_SMEM>>>(ahi, alo, w2hi, w2lo, out, nullptr, nullptr, C_);
    }
}